// round 15
// baseline (speedup 1.0000x reference)
#include <cuda_runtime.h>
#include <cuda_bf16.h>
#include <cstdint>

#define Hh 128
#define Ww 128
#define HW 16384
#define C 128
#define KK 9
#define EPS 1e-5f
#define NIMG 5

struct Ptr5 { const float* p[NIMG]; };

// ---------------- scratch (device globals; no runtime alloc) ----------------
__device__ float g_bufA[NIMG*HW*C];
__device__ float g_bufB[NIMG*HW*C];
__device__ float g_pre[NIMG*HW*C];
__device__ float g_offs[NIMG*HW*18];
__device__ float g_maskb[NIMG*HW*9];
__device__ uint32_t g_wtPh[2][KK*4*128*16];   // [b][k][cc][co][pair] bf16x2 hi
__device__ uint32_t g_wtPl[2][KK*4*128*16];
__device__ uint32_t g_effPh[2][KK*4*32*16];   // [b][k][cc][j][pair] bf16x2 hi
__device__ uint32_t g_effPl[2][KK*4*32*16];
__device__ float g_effb[2][32];
__device__ uint32_t g_pjH[1280*128];          // proj weights bf16x2 hi (K=256)
__device__ uint32_t g_pjL[1280*128];
__device__ float g_sumA[2*NIMG*128];
__device__ float g_sqA[2*NIMG*128];

__constant__ int c_ncos[5]   = {20,80,150,210,308};
__constant__ int c_pjbase[5] = {0,128,256,512,896};
__constant__ int c_coff[5]   = {0,20,100,250,460};
__constant__ int c_ccend[5]  = {4,4,8,8,8};

// ---------------- helpers ----------------
__device__ __forceinline__ uint32_t smem_u32(const void* p){
    uint32_t a;
    asm("{ .reg .u64 t; cvta.to.shared.u64 t, %1; cvt.u32.u64 %0, t; }" : "=r"(a) : "l"(p));
    return a;
}
__device__ __forceinline__ void bsplit2(float2 v, uint32_t &hp, uint32_t &lp_){
    __nv_bfloat162 h2 = __float22bfloat162_rn(v);
    float2 hf = __bfloat1622float2(h2);
    __nv_bfloat162 l2 = __float22bfloat162_rn(make_float2(v.x - hf.x, v.y - hf.y));
    hp = *reinterpret_cast<uint32_t*>(&h2);
    lp_ = *reinterpret_cast<uint32_t*>(&l2);
}
__device__ __forceinline__ void mma_bf16(float* d, uint32_t a0,uint32_t a1,uint32_t a2,uint32_t a3,
                                         uint32_t b0, uint32_t b1){
    asm volatile("mma.sync.aligned.m16n8k16.row.col.f32.bf16.bf16.f32 "
        "{%0,%1,%2,%3}, {%4,%5,%6,%7}, {%8,%9}, {%0,%1,%2,%3};"
        : "+f"(d[0]),"+f"(d[1]),"+f"(d[2]),"+f"(d[3])
        : "r"(a0),"r"(a1),"r"(a2),"r"(a3),"r"(b0),"r"(b1));
}
#define LDSM4(r, addr) \
    asm volatile("ldmatrix.sync.aligned.m8n8.x4.shared.b16 {%0,%1,%2,%3}, [%4];" \
        : "=r"((r)[0]),"=r"((r)[1]),"=r"((r)[2]),"=r"((r)[3]) : "r"(addr))
#define LDSM2(r, addr) \
    asm volatile("ldmatrix.sync.aligned.m8n8.x2.shared.b16 {%0,%1}, [%2];" \
        : "=r"((r)[0]),"=r"((r)[1]) : "r"(addr))

// 3-pass bf16-split MMA over one K=32 chunk via ldmatrix (stride 20 u32 rows).
__device__ __forceinline__ void mma_chunk3L(float d[2][4][4],
    uint32_t aH, uint32_t aL, uint32_t bH, uint32_t bL){
#pragma unroll
    for (int ks=0; ks<2; ks++){
        uint32_t ah[2][4], al[2][4];
        LDSM4(ah[0], aH + ks*32);
        LDSM4(ah[1], aH + 1280 + ks*32);
        LDSM4(al[0], aL + ks*32);
        LDSM4(al[1], aL + 1280 + ks*32);
        uint32_t bh[4][2];
#pragma unroll
        for (int nt=0;nt<4;nt++){
            LDSM2(bh[nt], bH + nt*640 + ks*32);
            mma_bf16(d[0][nt], ah[0][0],ah[0][1],ah[0][2],ah[0][3], bh[nt][0],bh[nt][1]);
            mma_bf16(d[1][nt], ah[1][0],ah[1][1],ah[1][2],ah[1][3], bh[nt][0],bh[nt][1]);
        }
#pragma unroll
        for (int nt=0;nt<4;nt++){
            uint32_t bl[2];
            LDSM2(bl, bL + nt*640 + ks*32);
            mma_bf16(d[0][nt], ah[0][0],ah[0][1],ah[0][2],ah[0][3], bl[0],bl[1]);
            mma_bf16(d[1][nt], ah[1][0],ah[1][1],ah[1][2],ah[1][3], bl[0],bl[1]);
        }
#pragma unroll
        for (int nt=0;nt<4;nt++){
            mma_bf16(d[0][nt], al[0][0],al[0][1],al[0][2],al[0][3], bh[nt][0],bh[nt][1]);
            mma_bf16(d[1][nt], al[1][0],al[1][1],al[1][2],al[1][3], bh[nt][0],bh[nt][1]);
        }
    }
}

// ---------------- prep kernels ----------------
__global__ void prep_wtP_kernel(const float* __restrict__ cw0, const float* __restrict__ cw1){
    int idx = blockIdx.x*blockDim.x + threadIdx.x;
    if (idx >= KK*4*128*16) return;
    int pr = idx & 15, co = (idx>>4)&127, cc = (idx>>11)&3, k = idx>>13;
    int ci0 = cc*32 + pr*2;
    uint32_t hp, lp;
    bsplit2(make_float2(cw0[(co*C+ci0)*KK + k], cw0[(co*C+ci0+1)*KK + k]), hp, lp);
    g_wtPh[0][idx]=hp; g_wtPl[0][idx]=lp;
    bsplit2(make_float2(cw1[(co*C+ci0)*KK + k], cw1[(co*C+ci0+1)*KK + k]), hp, lp);
    g_wtPh[1][idx]=hp; g_wtPl[1][idx]=lp;
}

__global__ void prep_effP_kernel(const float* __restrict__ cw, const float* __restrict__ ow,
                                 const float* __restrict__ mw, const float* __restrict__ cb, int b){
    int idx = blockIdx.x*blockDim.x + threadIdx.x;
    if (idx >= KK*4*32*16) return;
    int pr = idx&15, j = (idx>>4)&31, cc=(idx>>9)&3, k=idx>>11;
    int ci0 = cc*32 + pr*2;
    float s0=0.f, s1=0.f;
    if (j < 27){
        const float* P = (j<18) ? (ow + j*C) : (mw + (j-18)*C);
        for (int co=0; co<C; co++){
            float p = P[co];
            s0 += p*cw[(co*C+ci0)*KK + k];
            s1 += p*cw[(co*C+ci0+1)*KK + k];
        }
    }
    uint32_t hp, lp;
    bsplit2(make_float2(s0,s1), hp, lp);
    g_effPh[b][idx]=hp; g_effPl[b][idx]=lp;
    if (idx < 32){
        float bbv = 0.f;
        if (idx < 27){
            const float* P = (idx<18) ? (ow + idx*C) : (mw + (idx-18)*C);
            for (int co=0; co<C; co++) bbv += P[co]*cb[co];
        }
        g_effb[b][idx] = bbv;
    }
}

__global__ void prep_pj_kernel(Ptr5 wa, Ptr5 wb){
    int idx = blockIdx.x*blockDim.x + threadIdx.x;
    if (idx >= 1280*128) return;
    int u = idx & 127, row = idx >> 7;
    int img = 0;
#pragma unroll
    for (int i=1;i<5;i++) if (row >= c_pjbase[i]) img = i;
    int lco = row - c_pjbase[img];
    float v0=0.f, v1=0.f;
    if (lco < c_ncos[img]){
        if (u < 64){
            const float* w = wa.p[img];
            v0 = w[lco*C + u*2]; v1 = w[lco*C + u*2+1];
        } else {
            const float* w = wb.p[img];
            if (w){ v0 = w[lco*C + (u-64)*2]; v1 = w[lco*C + (u-64)*2+1]; }
        }
    }
    uint32_t hp, lp;
    bsplit2(make_float2(v0,v1), hp, lp);
    g_pjH[idx]=hp; g_pjL[idx]=lp;
}

__global__ void zero_sums_kernel(){
    int t = blockIdx.x*blockDim.x + threadIdx.x;
    if (t < 2*NIMG*128){ g_sumA[t]=0.f; g_sqA[t]=0.f; }
}

// ---------------- offsets conv via bf16 3-pass HMMA (PROVEN R11 version) ----------------
#define OC_SMEM (25560*4)
__global__ __launch_bounds__(256) void offcv3_kernel(Ptr5 xs, int b){
    extern __shared__ uint32_t su[];
    uint32_t* RH = su;
    uint32_t* RL = su + 7020;
    uint32_t* BOH = su + 14040;
    uint32_t* BOL = su + 19800;
    const int tid = threadIdx.x;
    const int h0 = blockIdx.x, img = blockIdx.y, pb = h0*128;
    const float* x = xs.p[img];
    float* offs = g_offs + (size_t)img*HW*18;
    float* mkb  = g_maskb + (size_t)img*HW*9;
    const int wid = tid>>5, lane = tid&31, lg = lane>>2, lc = lane&3;
    float d[4][4];
#pragma unroll
    for (int nt=0;nt<4;nt++)
#pragma unroll
        for (int i=0;i<4;i++) d[nt][i]=0.f;

    for (int cc=0; cc<4; cc++){
        __syncthreads();
#pragma unroll
        for (int t=0;t<2;t++){
            int idx = tid + t*256;
            if (idx < 384){
                int r = idx>>7, px = idx&127;
                int hh = h0 + r - 1;
                uint32_t base = (uint32_t)(r*130 + px + 1)*18;
                if (hh>=0 && hh<Hh){
                    const float4* src = (const float4*)(x + (((hh<<7)+px)<<7) + cc*32);
#pragma unroll
                    for (int i=0;i<8;i++){
                        float4 v = src[i];
                        uint32_t h0p,l0p,h1p,l1p;
                        bsplit2(make_float2(v.x,v.y), h0p,l0p);
                        bsplit2(make_float2(v.z,v.w), h1p,l1p);
                        *(uint2*)(RH + base + i*2) = make_uint2(h0p,h1p);
                        *(uint2*)(RL + base + i*2) = make_uint2(l0p,l1p);
                    }
                } else {
#pragma unroll
                    for (int i=0;i<8;i++){
                        *(uint2*)(RH + base + i*2) = make_uint2(0u,0u);
                        *(uint2*)(RL + base + i*2) = make_uint2(0u,0u);
                    }
                }
            }
        }
        if (tid < 96){
            int slot = tid>>4, pr = tid&15;
            int r = slot>>1, side = slot&1;
            uint32_t base = (uint32_t)(r*130 + (side?129:0))*18;
            RH[base+pr]=0u; RL[base+pr]=0u;
        }
#pragma unroll
        for (int t=0;t<18;t++){
            int idx = tid + t*256;
            int k = idx>>9, rr = idx & 511;
            int j = rr>>4, pr = rr&15;
            uint32_t gidx = (uint32_t)((k*4+cc)<<9) + (uint32_t)rr;
            BOH[(uint32_t)(k*32+j)*20 + pr] = g_effPh[b][gidx];
            BOL[(uint32_t)(k*32+j)*20 + pr] = g_effPl[b][gidx];
        }
        __syncthreads();
        for (int k=0;k<KK;k++){
            int ky = k/3, kx = k - ky*3 - 1;
#pragma unroll
            for (int ks=0; ks<2; ks++){
                uint32_t row = (uint32_t)(wid*16 + lg + kx + 1);
                uint32_t abase = ((uint32_t)ky*130 + row)*18 + ks*8 + lc;
                uint32_t ah0 = RH[abase],      ah1 = RH[abase + 144];
                uint32_t ah2 = RH[abase + 4],  ah3 = RH[abase + 148];
                uint32_t al0 = RL[abase],      al1 = RL[abase + 144];
                uint32_t al2 = RL[abase + 4],  al3 = RL[abase + 148];
#pragma unroll
                for (int nt=0;nt<4;nt++){
                    uint32_t bb = (uint32_t)(k*32 + nt*8 + lg)*20 + ks*8 + lc;
                    uint32_t b0 = BOH[bb], b1 = BOH[bb+4];
                    mma_bf16(d[nt], ah0,ah1,ah2,ah3, b0,b1);
                }
#pragma unroll
                for (int nt=0;nt<4;nt++){
                    uint32_t bb = (uint32_t)(k*32 + nt*8 + lg)*20 + ks*8 + lc;
                    uint32_t b0 = BOL[bb], b1 = BOL[bb+4];
                    mma_bf16(d[nt], ah0,ah1,ah2,ah3, b0,b1);
                }
#pragma unroll
                for (int nt=0;nt<4;nt++){
                    uint32_t bb = (uint32_t)(k*32 + nt*8 + lg)*20 + ks*8 + lc;
                    uint32_t b0 = BOH[bb], b1 = BOH[bb+4];
                    mma_bf16(d[nt], al0,al1,al2,al3, b0,b1);
                }
            }
        }
    }
    __syncthreads();
    float* Vs = (float*)su;  // [128][33]
#pragma unroll
    for (int nt=0;nt<4;nt++){
        int col = nt*8 + lc*2;
        int r0 = wid*16 + lg;
        Vs[r0*33 + col]       = d[nt][0] + g_effb[b][col];
        Vs[r0*33 + col + 1]   = d[nt][1] + g_effb[b][col+1];
        Vs[(r0+8)*33 + col]   = d[nt][2] + g_effb[b][col];
        Vs[(r0+8)*33 + col+1] = d[nt][3] + g_effb[b][col+1];
    }
    __syncthreads();
    if (tid < 128){
        int p = pb + tid;
        const float* v = Vs + tid*33;
#pragma unroll
        for (int j=0;j<18;j++) offs[p*18+j] = v[j];
        float mx = v[18];
#pragma unroll
        for (int j=19;j<27;j++) mx = fmaxf(mx, v[j]);
        float e[9]; float smv = 0.f;
#pragma unroll
        for (int j=0;j<9;j++){ e[j] = expf(v[18+j]-mx); smv += e[j]; }
        float inv = 1.f/smv;
#pragma unroll
        for (int j=0;j<9;j++) mkb[p*9+j] = e[j]*inv;
    }
}

// ---------------- pipelined sample-GEMM (q8 gather + ldmatrix; 2 CTAs/SM) ----------------
#define SGB 2560
#define SG7_SMEM (8*SGB*4)   // 81920 B
__global__ __launch_bounds__(512,2) void sg7_kernel(Ptr5 xs, const float* __restrict__ cbv,
                                                    int b, int s){
    extern __shared__ uint32_t su[];
    uint32_t* AHb[2]={su,         su + SGB};
    uint32_t* ALb[2]={su + 2*SGB, su + 3*SGB};
    uint32_t* BHb[2]={su + 4*SGB, su + 5*SGB};
    uint32_t* BLb[2]={su + 6*SGB, su + 7*SGB};
    const int tid = threadIdx.x;
    const int h0 = blockIdx.x, img = blockIdx.y, pb = h0*128;
    const float* x = xs.p[img];
    const float* offs = g_offs + (size_t)img*HW*18;
    const float* mkb  = g_maskb + (size_t)img*HW*9;
    const int q8 = tid & 7, pxA = tid >> 3;
    const int cob = tid >> 2, qb = tid & 3;
    const int wid = tid>>5, lane = tid&31, lg = lane>>2, lc = lane&3;
    const int warpM = wid&3, warpN = wid>>2;
    const int lr = lane&7, gg = lane>>3;

    const uint32_t sb = smem_u32(su);
    const uint32_t aPat = sb + (uint32_t)(((warpM*32 + (gg&1)*8 + lr)*20 + (gg>>1)*4)*4);
    const uint32_t bPat = sb + (uint32_t)(((warpN*32 + lr)*20 + (gg&1)*4)*4);

    float d[2][4][4];
#pragma unroll
    for (int mt=0;mt<2;mt++)
#pragma unroll
        for (int nt=0;nt<4;nt++)
#pragma unroll
            for (int i=0;i<4;i++) d[mt][nt][i]=0.f;

    float w00[2],w01[2],w10[2],w11[2],mk[2];
    int roff[2][4];
    int pk = -1;
    float4 gr[2][4];
    uint4 wbh, wbl;

    auto compute_tap = [&](int k){
#pragma unroll
        for (int sl=0; sl<2; sl++){
            int px = pxA + sl*64;
            int p = pb + px;
            float offy = offs[p*18 + 2*k];
            float offx = offs[p*18 + 2*k + 1];
            mk[sl] = mkb[p*9 + k];
            float py  = (float)(h0 - 1 + k/3) + offy;
            float pxf = (float)(px - 1 + (k - (k/3)*3)) + offx;
            float y0f = floorf(py), x0f = floorf(pxf);
            int y0 = (int)y0f, x0i = (int)x0f;
            float wy1 = py - y0f, wy0 = 1.f - wy1;
            float wx1 = pxf - x0f, wx0 = 1.f - wx1;
            int y1 = y0+1, x1i = x0i+1;
            bool vy0 = (y0>=0)&(y0<Hh), vy1 = (y1>=0)&(y1<Hh);
            bool vx0 = (x0i>=0)&(x0i<Ww), vx1 = (x1i>=0)&(x1i<Ww);
            w00[sl] = (vy0&&vx0)? wy0*wx0 : 0.f;
            w01[sl] = (vy0&&vx1)? wy0*wx1 : 0.f;
            w10[sl] = (vy1&&vx0)? wy1*wx0 : 0.f;
            w11[sl] = (vy1&&vx1)? wy1*wx1 : 0.f;
            int y0c = min(max(y0,0),Hh-1), y1c = min(max(y1,0),Hh-1);
            int x0c = min(max(x0i,0),Ww-1), x1c = min(max(x1i,0),Ww-1);
            roff[sl][0] = ((y0c<<7)+x0c)<<7;
            roff[sl][1] = ((y0c<<7)+x1c)<<7;
            roff[sl][2] = ((y1c<<7)+x0c)<<7;
            roff[sl][3] = ((y1c<<7)+x1c)<<7;
        }
    };
    auto gather = [&](int it){
        int k = it>>2, cc = it&3;
        if (k != pk){ compute_tap(k); pk = k; }
        int cg = cc*32 + q8*4;
#pragma unroll
        for (int sl=0; sl<2; sl++)
#pragma unroll
            for (int c=0; c<4; c++)
                gr[sl][c] = *(const float4*)(x + roff[sl][c] + cg);
        uint32_t base = (uint32_t)(((k*4+cc)*128 + cob)*16 + qb*4);
        wbh = *(const uint4*)(&g_wtPh[b][base]);
        wbl = *(const uint4*)(&g_wtPl[b][base]);
    };
    auto store_stage = [&](int buf){
#pragma unroll
        for (int sl=0; sl<2; sl++){
            float4 a = gr[sl][0], b4 = gr[sl][1], c4 = gr[sl][2], e4 = gr[sl][3];
            float4 o;
            o.x = mk[sl]*(w00[sl]*a.x + w01[sl]*b4.x + w10[sl]*c4.x + w11[sl]*e4.x);
            o.y = mk[sl]*(w00[sl]*a.y + w01[sl]*b4.y + w10[sl]*c4.y + w11[sl]*e4.y);
            o.z = mk[sl]*(w00[sl]*a.z + w01[sl]*b4.z + w10[sl]*c4.z + w11[sl]*e4.z);
            o.w = mk[sl]*(w00[sl]*a.w + w01[sl]*b4.w + w10[sl]*c4.w + w11[sl]*e4.w);
            uint32_t h0p,l0p,h1p,l1p;
            bsplit2(make_float2(o.x,o.y), h0p,l0p);
            bsplit2(make_float2(o.z,o.w), h1p,l1p);
            uint32_t abase = (uint32_t)(pxA + sl*64)*20 + q8*2;
            *(uint2*)(AHb[buf]+abase) = make_uint2(h0p,h1p);
            *(uint2*)(ALb[buf]+abase) = make_uint2(l0p,l1p);
        }
        uint32_t bbase = (uint32_t)cob*20 + qb*4;
        *(uint4*)(BHb[buf]+bbase) = wbh;
        *(uint4*)(BLb[buf]+bbase) = wbl;
    };

    gather(0);
    for (int it=0; it<36; it++){
        int buf = it & 1;
        store_stage(buf);
        __syncthreads();
        if (it < 35) gather(it+1);
        uint32_t boff = (uint32_t)buf*(SGB*4);
        mma_chunk3L(d, aPat + boff, aPat + 2*(SGB*4) + boff,
                       bPat + 4*(SGB*4) + boff, bPat + 6*(SGB*4) + boff);
    }
    __syncthreads();

    // epilogue: bias + g_pre + fused stats
    float* Vs  = (float*)su;        // [128][132]
    float* Ps  = Vs + 16896;
    float* Ps2 = Ps + 512;
#pragma unroll
    for (int mt=0;mt<2;mt++){
        int r0 = warpM*32 + mt*16 + lg;
#pragma unroll
        for (int nt=0;nt<4;nt++){
            int co0 = warpN*32 + nt*8 + lc*2;
            float b0v = cbv[co0], b1v = cbv[co0+1];
            *(float2*)(Vs + r0*132 + co0)     = make_float2(d[mt][nt][0]+b0v, d[mt][nt][1]+b1v);
            *(float2*)(Vs + (r0+8)*132 + co0) = make_float2(d[mt][nt][2]+b0v, d[mt][nt][3]+b1v);
        }
    }
    __syncthreads();
    float* preo = g_pre + (size_t)img*HW*C;
#pragma unroll
    for (int t=0;t<32;t++){
        int idx = tid + t*512;
        int p2 = idx>>7, co = idx&127;
        preo[(pb+p2)*C + co] = Vs[p2*132 + co];
    }
    {
        int co = tid&127, qq = tid>>7;
        float S=0.f, Q=0.f;
#pragma unroll 8
        for (int i=0;i<32;i++){ float v = Vs[(qq*32+i)*132+co]; S += v; Q += v*v; }
        Ps[qq*128+co] = S; Ps2[qq*128+co] = Q;
        __syncthreads();
        if (tid < 128){
            float SS = Ps[tid]+Ps[128+tid]+Ps[256+tid]+Ps[384+tid];
            float QQ = Ps2[tid]+Ps2[128+tid]+Ps2[256+tid]+Ps2[384+tid];
            atomicAdd(&g_sumA[(s*NIMG+img)*128+tid], SS);
            atomicAdd(&g_sqA[(s*NIMG+img)*128+tid], QQ);
        }
    }
}

// ---------------- instance-norm apply ----------------
__global__ void normrelu2_kernel(const float* __restrict__ bg, const float* __restrict__ bb,
                                 float* __restrict__ outbase, int s){
    int img = blockIdx.y;
    int idx = blockIdx.x*blockDim.x + threadIdx.x;
    int c = idx & 127;
    float mu = g_sumA[(s*NIMG+img)*128+c] * (1.f/HW);
    float var = g_sqA[(s*NIMG+img)*128+c] * (1.f/HW) - mu*mu;
    float v = (g_pre[(size_t)img*HW*C + idx]-mu)*rsqrtf(var+EPS)*bg[c] + bb[c];
    outbase[(size_t)img*HW*C + idx] = fmaxf(v, 0.f);
}

// ---------------- projections via HMMA (K=256: xc || xp; NCC skip; ldmatrix) ----------------
#define PJ_SMEM (8*SGB*4)
__global__ __launch_bounds__(512,1) void projH_kernel(const float* __restrict__ xcbase, Ptr5 xps,
                                                      float* __restrict__ out){
    const int img = blockIdx.z;
    const int nco = c_ncos[img];
    const int ct = blockIdx.y;
    if (ct*128 >= nco) return;
    extern __shared__ uint32_t su[];
    uint32_t* AHb[2]={su,         su + SGB};
    uint32_t* ALb[2]={su + 2*SGB, su + 3*SGB};
    uint32_t* BHb[2]={su + 4*SGB, su + 5*SGB};
    uint32_t* BLb[2]={su + 6*SGB, su + 7*SGB};
    const int tid = threadIdx.x;
    const int h0 = blockIdx.x, pb = h0*128;
    const float* xc = xcbase + (size_t)img*HW*C;
    const float* xp = xps.p[img];
    const int px = tid>>2, q4 = tid&3;
    const int wid = tid>>5, lane = tid&31, lg = lane>>2, lc = lane&3;
    const int warpM = wid&3, warpN = wid>>2;
    const int rowbase = c_pjbase[img] + ct*128;
    const int NCC = c_ccend[img];
    const int lr = lane&7, gg = lane>>3;

    const uint32_t sb = smem_u32(su);
    const uint32_t aPat = sb + (uint32_t)(((warpM*32 + (gg&1)*8 + lr)*20 + (gg>>1)*4)*4);
    const uint32_t bPat = sb + (uint32_t)(((warpN*32 + lr)*20 + (gg&1)*4)*4);

    float d[2][4][4];
#pragma unroll
    for (int mt=0;mt<2;mt++)
#pragma unroll
        for (int nt=0;nt<4;nt++)
#pragma unroll
            for (int i=0;i<4;i++) d[mt][nt][i]=0.f;

    float4 gr[2];
    uint4 wbh, wbl;
    auto load_chunk = [&](int cc){
        const float* src = (cc<4) ? (xc + (size_t)(pb+px)*C + cc*32 + q4*8)
                                  : (xp + (size_t)(pb+px)*C + (cc-4)*32 + q4*8);
        gr[0] = ((const float4*)src)[0];
        gr[1] = ((const float4*)src)[1];
        uint32_t base = (uint32_t)((rowbase+px)*128 + cc*16 + q4*4);
        wbh = *(const uint4*)(&g_pjH[base]);
        wbl = *(const uint4*)(&g_pjL[base]);
    };
    auto store_stage = [&](int buf){
        uint32_t hh[4], ll[4];
        bsplit2(make_float2(gr[0].x,gr[0].y), hh[0], ll[0]);
        bsplit2(make_float2(gr[0].z,gr[0].w), hh[1], ll[1]);
        bsplit2(make_float2(gr[1].x,gr[1].y), hh[2], ll[2]);
        bsplit2(make_float2(gr[1].z,gr[1].w), hh[3], ll[3]);
        uint32_t abase = (uint32_t)px*20 + q4*4;
        *(uint4*)(AHb[buf]+abase) = make_uint4(hh[0],hh[1],hh[2],hh[3]);
        *(uint4*)(ALb[buf]+abase) = make_uint4(ll[0],ll[1],ll[2],ll[3]);
        *(uint4*)(BHb[buf]+abase) = wbh;
        *(uint4*)(BLb[buf]+abase) = wbl;
    };

    load_chunk(0); store_stage(0);
    __syncthreads();
    for (int cc=0; cc<NCC; cc++){
        if (cc < NCC-1) load_chunk(cc+1);
        uint32_t boff = (uint32_t)(cc&1)*(SGB*4);
        mma_chunk3L(d, aPat + boff, aPat + 2*(SGB*4) + boff,
                       bPat + 4*(SGB*4) + boff, bPat + 6*(SGB*4) + boff);
        if (cc < NCC-1) store_stage((cc+1)&1);
        __syncthreads();
    }

    float* Vs = (float*)su;   // [128][132]
#pragma unroll
    for (int mt=0;mt<2;mt++){
        int r0 = warpM*32 + mt*16 + lg;
#pragma unroll
        for (int nt=0;nt<4;nt++){
            int co0 = warpN*32 + nt*8 + lc*2;
            *(float2*)(Vs + r0*132 + co0)     = make_float2(d[mt][nt][0], d[mt][nt][1]);
            *(float2*)(Vs + (r0+8)*132 + co0) = make_float2(d[mt][nt][2], d[mt][nt][3]);
        }
    }
    __syncthreads();
    {
        int co = tid>>2, sub = tid&3;
        int cog = ct*128 + co;
        if (cog < nco){
            float* dst = out + (size_t)(c_coff[img]+cog)*HW + pb + sub*32;
#pragma unroll
            for (int j=0;j<8;j++){
                int r = sub*32 + j*4;
                float4 o = make_float4(Vs[r*132+co], Vs[(r+1)*132+co],
                                       Vs[(r+2)*132+co], Vs[(r+3)*132+co]);
                *(float4*)(dst + j*4) = o;
            }
        }
    }
}

// ---------------- final layernorm over W ----------------
__global__ __launch_bounds__(128) void ln_kernel(float* __restrict__ o, const float* __restrict__ lnw,
                                                 const float* __restrict__ lnb){
    __shared__ float ss[4], ssq[4];
    int row = blockIdx.x;
    float* r = o + (size_t)row*128;
    int t = threadIdx.x;
    float v = r[t];
    float s = v, sq = v*v;
#pragma unroll
    for (int off=16; off; off>>=1){
        s  += __shfl_down_sync(0xffffffffu, s, off);
        sq += __shfl_down_sync(0xffffffffu, sq, off);
    }
    int wid = t >> 5, lane = t & 31;
    if (lane==0){ ss[wid]=s; ssq[wid]=sq; }
    __syncthreads();
    float S  = ss[0]+ss[1]+ss[2]+ss[3];
    float SQ = ssq[0]+ssq[1]+ssq[2]+ssq[3];
    float mu = S*(1.f/128.f);
    float var = SQ*(1.f/128.f) - mu*mu;
    r[t] = (v-mu)*rsqrtf(var+EPS)*lnw[t] + lnb[t];
}

// ---------------- host orchestration ----------------
extern "C" void kernel_launch(void* const* d_in, const int* in_sizes, int n_in,
                              void* d_out, int out_size){
    (void)in_sizes; (void)n_in; (void)out_size;
    const float* x[5];
    for (int i=0;i<5;i++) x[i] = (const float*)d_in[i];
    const float* cw[2] = {(const float*)d_in[5],  (const float*)d_in[11]};
    const float* cb[2] = {(const float*)d_in[6],  (const float*)d_in[12]};
    const float* ow[2] = {(const float*)d_in[7],  (const float*)d_in[13]};
    const float* mw[2] = {(const float*)d_in[8],  (const float*)d_in[14]};
    const float* bg[2] = {(const float*)d_in[9],  (const float*)d_in[15]};
    const float* bb[2] = {(const float*)d_in[10], (const float*)d_in[16]};
    const float* pwa[5] = {(const float*)d_in[17], (const float*)d_in[18], (const float*)d_in[19],
                           (const float*)d_in[21], (const float*)d_in[23]};
    const float* pwb[5] = {nullptr, nullptr, (const float*)d_in[20],
                           (const float*)d_in[22], (const float*)d_in[24]};
    const float* lnw = (const float*)d_in[25];
    const float* lnb = (const float*)d_in[26];
    float* outp = (float*)d_out;

    float *pA=nullptr, *pB=nullptr;
    cudaGetSymbolAddress((void**)&pA, g_bufA);
    cudaGetSymbolAddress((void**)&pB, g_bufB);

    Ptr5 xs0, xsA, wav, wbv;
    for (int i=0;i<5;i++){
        xs0.p[i] = x[i];
        xsA.p[i] = pA + (size_t)i*HW*C;
        wav.p[i] = pwa[i];
        wbv.p[i] = pwb[i];
    }

    cudaFuncSetAttribute(offcv3_kernel, cudaFuncAttributeMaxDynamicSharedMemorySize, OC_SMEM);
    cudaFuncSetAttribute(sg7_kernel, cudaFuncAttributeMaxDynamicSharedMemorySize, SG7_SMEM);
    cudaFuncSetAttribute(projH_kernel, cudaFuncAttributeMaxDynamicSharedMemorySize, PJ_SMEM);
    // Force max shared-memory carveout so 2 CTAs/SM can co-reside.
    cudaFuncSetAttribute(offcv3_kernel, cudaFuncAttributePreferredSharedMemoryCarveout, 100);
    cudaFuncSetAttribute(sg7_kernel, cudaFuncAttributePreferredSharedMemoryCarveout, 100);
    cudaFuncSetAttribute(projH_kernel, cudaFuncAttributePreferredSharedMemoryCarveout, 100);

    prep_wtP_kernel<<<(KK*4*128*16+255)/256, 256>>>(cw[0], cw[1]);
    prep_effP_kernel<<<(KK*4*32*16+255)/256, 256>>>(cw[0], ow[0], mw[0], cb[0], 0);
    prep_effP_kernel<<<(KK*4*32*16+255)/256, 256>>>(cw[1], ow[1], mw[1], cb[1], 1);
    prep_pj_kernel<<<(1280*128+255)/256, 256>>>(wav, wbv);
    zero_sums_kernel<<<5, 256>>>();

    // stage 1 (all images)
    offcv3_kernel<<<dim3(128,5), 256, OC_SMEM>>>(xs0, 0);
    sg7_kernel<<<dim3(128,5), 512, SG7_SMEM>>>(xs0, cb[0], 0, 0);
    normrelu2_kernel<<<dim3(HW*C/256,5), 256>>>(bg[0], bb[0], pA, 0);
    // stage 2 (all images)
    offcv3_kernel<<<dim3(128,5), 256, OC_SMEM>>>(xsA, 1);
    sg7_kernel<<<dim3(128,5), 512, SG7_SMEM>>>(xsA, cb[1], 1, 1);
    normrelu2_kernel<<<dim3(HW*C/256,5), 256>>>(bg[1], bb[1], pB, 1);
    // projections + final LN
    projH_kernel<<<dim3(128,3,5), 512, PJ_SMEM>>>(pB, xs0, outp);
    ln_kernel<<<768*Hh, 128>>>(outp, lnw, lnb);
}

// round 17
// speedup vs baseline: 2.0507x; 2.0507x over previous
#include <cuda_runtime.h>
#include <cuda_bf16.h>
#include <cstdint>

#define Hh 128
#define Ww 128
#define HW 16384
#define C 128
#define KK 9
#define EPS 1e-5f
#define NIMG 5

struct Ptr5 { const float* p[NIMG]; };

// ---------------- scratch (device globals; no runtime alloc) ----------------
__device__ float g_bufA[NIMG*HW*C];
__device__ float g_bufB[NIMG*HW*C];
__device__ float g_pre[NIMG*HW*C];
__device__ float g_offs[NIMG*HW*18];
__device__ float g_maskb[NIMG*HW*9];
__device__ uint32_t g_wtPh[2][KK*4*128*16];   // [b][k][cc][co][pair] bf16x2 hi
__device__ uint32_t g_wtPl[2][KK*4*128*16];
__device__ uint32_t g_effPh[2][KK*4*32*16];   // [b][k][cc][j][pair] bf16x2 hi
__device__ uint32_t g_effPl[2][KK*4*32*16];
__device__ float g_effb[2][32];
__device__ uint32_t g_pjH[1280*128];          // proj weights bf16x2 hi (K=256)
__device__ uint32_t g_pjL[1280*128];
__device__ float g_sumA[2*NIMG*128];
__device__ float g_sqA[2*NIMG*128];

__constant__ int c_ncos[5]   = {20,80,150,210,308};
__constant__ int c_pjbase[5] = {0,128,256,512,896};
__constant__ int c_coff[5]   = {0,20,100,250,460};
__constant__ int c_ccend[5]  = {4,4,8,8,8};

// ---------------- helpers ----------------
__device__ __forceinline__ uint32_t smem_u32(const void* p){
    uint32_t a;
    asm("{ .reg .u64 t; cvta.to.shared.u64 t, %1; cvt.u32.u64 %0, t; }" : "=r"(a) : "l"(p));
    return a;
}
__device__ __forceinline__ void bsplit2(float2 v, uint32_t &hp, uint32_t &lp_){
    __nv_bfloat162 h2 = __float22bfloat162_rn(v);
    float2 hf = __bfloat1622float2(h2);
    __nv_bfloat162 l2 = __float22bfloat162_rn(make_float2(v.x - hf.x, v.y - hf.y));
    hp = *reinterpret_cast<uint32_t*>(&h2);
    lp_ = *reinterpret_cast<uint32_t*>(&l2);
}
__device__ __forceinline__ void mma_bf16(float* d, uint32_t a0,uint32_t a1,uint32_t a2,uint32_t a3,
                                         uint32_t b0, uint32_t b1){
    asm volatile("mma.sync.aligned.m16n8k16.row.col.f32.bf16.bf16.f32 "
        "{%0,%1,%2,%3}, {%4,%5,%6,%7}, {%8,%9}, {%0,%1,%2,%3};"
        : "+f"(d[0]),"+f"(d[1]),"+f"(d[2]),"+f"(d[3])
        : "r"(a0),"r"(a1),"r"(a2),"r"(a3),"r"(b0),"r"(b1));
}
#define LDSM4(r, addr) \
    asm volatile("ldmatrix.sync.aligned.m8n8.x4.shared.b16 {%0,%1,%2,%3}, [%4];" \
        : "=r"((r)[0]),"=r"((r)[1]),"=r"((r)[2]),"=r"((r)[3]) : "r"(addr))
#define LDSM2(r, addr) \
    asm volatile("ldmatrix.sync.aligned.m8n8.x2.shared.b16 {%0,%1}, [%2];" \
        : "=r"((r)[0]),"=r"((r)[1]) : "r"(addr))

// 3-pass bf16-split MMA over one K=32 chunk via ldmatrix (stride 20 u32 rows).
__device__ __forceinline__ void mma_chunk3L(float d[2][4][4],
    uint32_t aH, uint32_t aL, uint32_t bH, uint32_t bL){
#pragma unroll
    for (int ks=0; ks<2; ks++){
        uint32_t ah[2][4], al[2][4];
        LDSM4(ah[0], aH + ks*32);
        LDSM4(ah[1], aH + 1280 + ks*32);
        LDSM4(al[0], aL + ks*32);
        LDSM4(al[1], aL + 1280 + ks*32);
        uint32_t bh[4][2];
#pragma unroll
        for (int nt=0;nt<4;nt++){
            LDSM2(bh[nt], bH + nt*640 + ks*32);
            mma_bf16(d[0][nt], ah[0][0],ah[0][1],ah[0][2],ah[0][3], bh[nt][0],bh[nt][1]);
            mma_bf16(d[1][nt], ah[1][0],ah[1][1],ah[1][2],ah[1][3], bh[nt][0],bh[nt][1]);
        }
#pragma unroll
        for (int nt=0;nt<4;nt++){
            uint32_t bl[2];
            LDSM2(bl, bL + nt*640 + ks*32);
            mma_bf16(d[0][nt], ah[0][0],ah[0][1],ah[0][2],ah[0][3], bl[0],bl[1]);
            mma_bf16(d[1][nt], ah[1][0],ah[1][1],ah[1][2],ah[1][3], bl[0],bl[1]);
        }
#pragma unroll
        for (int nt=0;nt<4;nt++){
            mma_bf16(d[0][nt], al[0][0],al[0][1],al[0][2],al[0][3], bh[nt][0],bh[nt][1]);
            mma_bf16(d[1][nt], al[1][0],al[1][1],al[1][2],al[1][3], bh[nt][0],bh[nt][1]);
        }
    }
}

// ---------------- prep kernels ----------------
__global__ void prep_wtP_kernel(const float* __restrict__ cw0, const float* __restrict__ cw1){
    int idx = blockIdx.x*blockDim.x + threadIdx.x;
    if (idx >= KK*4*128*16) return;
    int pr = idx & 15, co = (idx>>4)&127, cc = (idx>>11)&3, k = idx>>13;
    int ci0 = cc*32 + pr*2;
    uint32_t hp, lp;
    bsplit2(make_float2(cw0[(co*C+ci0)*KK + k], cw0[(co*C+ci0+1)*KK + k]), hp, lp);
    g_wtPh[0][idx]=hp; g_wtPl[0][idx]=lp;
    bsplit2(make_float2(cw1[(co*C+ci0)*KK + k], cw1[(co*C+ci0+1)*KK + k]), hp, lp);
    g_wtPh[1][idx]=hp; g_wtPl[1][idx]=lp;
}

__global__ void prep_effP_kernel(const float* __restrict__ cw, const float* __restrict__ ow,
                                 const float* __restrict__ mw, const float* __restrict__ cb, int b){
    int idx = blockIdx.x*blockDim.x + threadIdx.x;
    if (idx >= KK*4*32*16) return;
    int pr = idx&15, j = (idx>>4)&31, cc=(idx>>9)&3, k=idx>>11;
    int ci0 = cc*32 + pr*2;
    float s0=0.f, s1=0.f;
    if (j < 27){
        const float* P = (j<18) ? (ow + j*C) : (mw + (j-18)*C);
        for (int co=0; co<C; co++){
            float p = P[co];
            s0 += p*cw[(co*C+ci0)*KK + k];
            s1 += p*cw[(co*C+ci0+1)*KK + k];
        }
    }
    uint32_t hp, lp;
    bsplit2(make_float2(s0,s1), hp, lp);
    g_effPh[b][idx]=hp; g_effPl[b][idx]=lp;
    if (idx < 32){
        float bbv = 0.f;
        if (idx < 27){
            const float* P = (idx<18) ? (ow + idx*C) : (mw + (idx-18)*C);
            for (int co=0; co<C; co++) bbv += P[co]*cb[co];
        }
        g_effb[b][idx] = bbv;
    }
}

__global__ void prep_pj_kernel(Ptr5 wa, Ptr5 wb){
    int idx = blockIdx.x*blockDim.x + threadIdx.x;
    if (idx >= 1280*128) return;
    int u = idx & 127, row = idx >> 7;
    int img = 0;
#pragma unroll
    for (int i=1;i<5;i++) if (row >= c_pjbase[i]) img = i;
    int lco = row - c_pjbase[img];
    float v0=0.f, v1=0.f;
    if (lco < c_ncos[img]){
        if (u < 64){
            const float* w = wa.p[img];
            v0 = w[lco*C + u*2]; v1 = w[lco*C + u*2+1];
        } else {
            const float* w = wb.p[img];
            if (w){ v0 = w[lco*C + (u-64)*2]; v1 = w[lco*C + (u-64)*2+1]; }
        }
    }
    uint32_t hp, lp;
    bsplit2(make_float2(v0,v1), hp, lp);
    g_pjH[idx]=hp; g_pjL[idx]=lp;
}

__global__ void zero_sums_kernel(){
    int t = blockIdx.x*blockDim.x + threadIdx.x;
    if (t < 2*NIMG*128){ g_sumA[t]=0.f; g_sqA[t]=0.f; }
}

// ---------------- offsets conv via bf16 3-pass HMMA (PROVEN R11 version) ----------------
#define OC_SMEM (25560*4)
__global__ __launch_bounds__(256) void offcv3_kernel(Ptr5 xs, int b){
    extern __shared__ uint32_t su[];
    uint32_t* RH = su;
    uint32_t* RL = su + 7020;
    uint32_t* BOH = su + 14040;
    uint32_t* BOL = su + 19800;
    const int tid = threadIdx.x;
    const int h0 = blockIdx.x, img = blockIdx.y, pb = h0*128;
    const float* x = xs.p[img];
    float* offs = g_offs + (size_t)img*HW*18;
    float* mkb  = g_maskb + (size_t)img*HW*9;
    const int wid = tid>>5, lane = tid&31, lg = lane>>2, lc = lane&3;
    float d[4][4];
#pragma unroll
    for (int nt=0;nt<4;nt++)
#pragma unroll
        for (int i=0;i<4;i++) d[nt][i]=0.f;

    for (int cc=0; cc<4; cc++){
        __syncthreads();
#pragma unroll
        for (int t=0;t<2;t++){
            int idx = tid + t*256;
            if (idx < 384){
                int r = idx>>7, px = idx&127;
                int hh = h0 + r - 1;
                uint32_t base = (uint32_t)(r*130 + px + 1)*18;
                if (hh>=0 && hh<Hh){
                    const float4* src = (const float4*)(x + (((hh<<7)+px)<<7) + cc*32);
#pragma unroll
                    for (int i=0;i<8;i++){
                        float4 v = src[i];
                        uint32_t h0p,l0p,h1p,l1p;
                        bsplit2(make_float2(v.x,v.y), h0p,l0p);
                        bsplit2(make_float2(v.z,v.w), h1p,l1p);
                        *(uint2*)(RH + base + i*2) = make_uint2(h0p,h1p);
                        *(uint2*)(RL + base + i*2) = make_uint2(l0p,l1p);
                    }
                } else {
#pragma unroll
                    for (int i=0;i<8;i++){
                        *(uint2*)(RH + base + i*2) = make_uint2(0u,0u);
                        *(uint2*)(RL + base + i*2) = make_uint2(0u,0u);
                    }
                }
            }
        }
        if (tid < 96){
            int slot = tid>>4, pr = tid&15;
            int r = slot>>1, side = slot&1;
            uint32_t base = (uint32_t)(r*130 + (side?129:0))*18;
            RH[base+pr]=0u; RL[base+pr]=0u;
        }
#pragma unroll
        for (int t=0;t<18;t++){
            int idx = tid + t*256;
            int k = idx>>9, rr = idx & 511;
            int j = rr>>4, pr = rr&15;
            uint32_t gidx = (uint32_t)((k*4+cc)<<9) + (uint32_t)rr;
            BOH[(uint32_t)(k*32+j)*20 + pr] = g_effPh[b][gidx];
            BOL[(uint32_t)(k*32+j)*20 + pr] = g_effPl[b][gidx];
        }
        __syncthreads();
        for (int k=0;k<KK;k++){
            int ky = k/3, kx = k - ky*3 - 1;
#pragma unroll
            for (int ks=0; ks<2; ks++){
                uint32_t row = (uint32_t)(wid*16 + lg + kx + 1);
                uint32_t abase = ((uint32_t)ky*130 + row)*18 + ks*8 + lc;
                uint32_t ah0 = RH[abase],      ah1 = RH[abase + 144];
                uint32_t ah2 = RH[abase + 4],  ah3 = RH[abase + 148];
                uint32_t al0 = RL[abase],      al1 = RL[abase + 144];
                uint32_t al2 = RL[abase + 4],  al3 = RL[abase + 148];
#pragma unroll
                for (int nt=0;nt<4;nt++){
                    uint32_t bb = (uint32_t)(k*32 + nt*8 + lg)*20 + ks*8 + lc;
                    uint32_t b0 = BOH[bb], b1 = BOH[bb+4];
                    mma_bf16(d[nt], ah0,ah1,ah2,ah3, b0,b1);
                }
#pragma unroll
                for (int nt=0;nt<4;nt++){
                    uint32_t bb = (uint32_t)(k*32 + nt*8 + lg)*20 + ks*8 + lc;
                    uint32_t b0 = BOL[bb], b1 = BOL[bb+4];
                    mma_bf16(d[nt], ah0,ah1,ah2,ah3, b0,b1);
                }
#pragma unroll
                for (int nt=0;nt<4;nt++){
                    uint32_t bb = (uint32_t)(k*32 + nt*8 + lg)*20 + ks*8 + lc;
                    uint32_t b0 = BOH[bb], b1 = BOH[bb+4];
                    mma_bf16(d[nt], al0,al1,al2,al3, b0,b1);
                }
            }
        }
    }
    __syncthreads();
    float* Vs = (float*)su;  // [128][33]
#pragma unroll
    for (int nt=0;nt<4;nt++){
        int col = nt*8 + lc*2;
        int r0 = wid*16 + lg;
        Vs[r0*33 + col]       = d[nt][0] + g_effb[b][col];
        Vs[r0*33 + col + 1]   = d[nt][1] + g_effb[b][col+1];
        Vs[(r0+8)*33 + col]   = d[nt][2] + g_effb[b][col];
        Vs[(r0+8)*33 + col+1] = d[nt][3] + g_effb[b][col+1];
    }
    __syncthreads();
    if (tid < 128){
        int p = pb + tid;
        const float* v = Vs + tid*33;
#pragma unroll
        for (int j=0;j<18;j++) offs[p*18+j] = v[j];
        float mx = v[18];
#pragma unroll
        for (int j=19;j<27;j++) mx = fmaxf(mx, v[j]);
        float e[9]; float smv = 0.f;
#pragma unroll
        for (int j=0;j<9;j++){ e[j] = expf(v[18+j]-mx); smv += e[j]; }
        float inv = 1.f/smv;
#pragma unroll
        for (int j=0;j<9;j++) mkb[p*9+j] = e[j]*inv;
    }
}

// ---------------- pipelined sample-GEMM (q8 gather + ldmatrix fragments) ----------------
#define SGB 2560
#define SG7_SMEM (8*SGB*4)   // 81920 B
__global__ __launch_bounds__(512,1) void sg7_kernel(Ptr5 xs, const float* __restrict__ cbv,
                                                    int b, int s){
    extern __shared__ uint32_t su[];
    uint32_t* AHb[2]={su,         su + SGB};
    uint32_t* ALb[2]={su + 2*SGB, su + 3*SGB};
    uint32_t* BHb[2]={su + 4*SGB, su + 5*SGB};
    uint32_t* BLb[2]={su + 6*SGB, su + 7*SGB};
    const int tid = threadIdx.x;
    const int h0 = blockIdx.x, img = blockIdx.y, pb = h0*128;
    const float* x = xs.p[img];
    const float* offs = g_offs + (size_t)img*HW*18;
    const float* mkb  = g_maskb + (size_t)img*HW*9;
    const int q8 = tid & 7, pxA = tid >> 3;
    const int cob = tid >> 2, qb = tid & 3;
    const int wid = tid>>5, lane = tid&31, lg = lane>>2, lc = lane&3;
    const int warpM = wid&3, warpN = wid>>2;
    const int lr = lane&7, gg = lane>>3;

    const uint32_t sb = smem_u32(su);
    const uint32_t aPat = sb + (uint32_t)(((warpM*32 + (gg&1)*8 + lr)*20 + (gg>>1)*4)*4);
    const uint32_t bPat = sb + (uint32_t)(((warpN*32 + lr)*20 + (gg&1)*4)*4);

    float d[2][4][4];
#pragma unroll
    for (int mt=0;mt<2;mt++)
#pragma unroll
        for (int nt=0;nt<4;nt++)
#pragma unroll
            for (int i=0;i<4;i++) d[mt][nt][i]=0.f;

    float w00[2],w01[2],w10[2],w11[2],mk[2];
    int roff[2][4];
    int pk = -1;
    float4 gr[2][4];
    uint4 wbh, wbl;

    auto compute_tap = [&](int k){
#pragma unroll
        for (int sl=0; sl<2; sl++){
            int px = pxA + sl*64;
            int p = pb + px;
            float offy = offs[p*18 + 2*k];
            float offx = offs[p*18 + 2*k + 1];
            mk[sl] = mkb[p*9 + k];
            float py  = (float)(h0 - 1 + k/3) + offy;
            float pxf = (float)(px - 1 + (k - (k/3)*3)) + offx;
            float y0f = floorf(py), x0f = floorf(pxf);
            int y0 = (int)y0f, x0i = (int)x0f;
            float wy1 = py - y0f, wy0 = 1.f - wy1;
            float wx1 = pxf - x0f, wx0 = 1.f - wx1;
            int y1 = y0+1, x1i = x0i+1;
            bool vy0 = (y0>=0)&(y0<Hh), vy1 = (y1>=0)&(y1<Hh);
            bool vx0 = (x0i>=0)&(x0i<Ww), vx1 = (x1i>=0)&(x1i<Ww);
            w00[sl] = (vy0&&vx0)? wy0*wx0 : 0.f;
            w01[sl] = (vy0&&vx1)? wy0*wx1 : 0.f;
            w10[sl] = (vy1&&vx0)? wy1*wx0 : 0.f;
            w11[sl] = (vy1&&vx1)? wy1*wx1 : 0.f;
            int y0c = min(max(y0,0),Hh-1), y1c = min(max(y1,0),Hh-1);
            int x0c = min(max(x0i,0),Ww-1), x1c = min(max(x1i,0),Ww-1);
            roff[sl][0] = ((y0c<<7)+x0c)<<7;
            roff[sl][1] = ((y0c<<7)+x1c)<<7;
            roff[sl][2] = ((y1c<<7)+x0c)<<7;
            roff[sl][3] = ((y1c<<7)+x1c)<<7;
        }
    };
    auto gather = [&](int it){
        int k = it>>2, cc = it&3;
        if (k != pk){ compute_tap(k); pk = k; }
        int cg = cc*32 + q8*4;
#pragma unroll
        for (int sl=0; sl<2; sl++)
#pragma unroll
            for (int c=0; c<4; c++)
                gr[sl][c] = *(const float4*)(x + roff[sl][c] + cg);
        uint32_t base = (uint32_t)(((k*4+cc)*128 + cob)*16 + qb*4);
        wbh = *(const uint4*)(&g_wtPh[b][base]);
        wbl = *(const uint4*)(&g_wtPl[b][base]);
    };
    auto store_stage = [&](int buf){
#pragma unroll
        for (int sl=0; sl<2; sl++){
            float4 a = gr[sl][0], b4 = gr[sl][1], c4 = gr[sl][2], e4 = gr[sl][3];
            float4 o;
            o.x = mk[sl]*(w00[sl]*a.x + w01[sl]*b4.x + w10[sl]*c4.x + w11[sl]*e4.x);
            o.y = mk[sl]*(w00[sl]*a.y + w01[sl]*b4.y + w10[sl]*c4.y + w11[sl]*e4.y);
            o.z = mk[sl]*(w00[sl]*a.z + w01[sl]*b4.z + w10[sl]*c4.z + w11[sl]*e4.z);
            o.w = mk[sl]*(w00[sl]*a.w + w01[sl]*b4.w + w10[sl]*c4.w + w11[sl]*e4.w);
            uint32_t h0p,l0p,h1p,l1p;
            bsplit2(make_float2(o.x,o.y), h0p,l0p);
            bsplit2(make_float2(o.z,o.w), h1p,l1p);
            uint32_t abase = (uint32_t)(pxA + sl*64)*20 + q8*2;
            *(uint2*)(AHb[buf]+abase) = make_uint2(h0p,h1p);
            *(uint2*)(ALb[buf]+abase) = make_uint2(l0p,l1p);
        }
        uint32_t bbase = (uint32_t)cob*20 + qb*4;
        *(uint4*)(BHb[buf]+bbase) = wbh;
        *(uint4*)(BLb[buf]+bbase) = wbl;
    };

    gather(0);
    for (int it=0; it<36; it++){
        int buf = it & 1;
        store_stage(buf);
        __syncthreads();
        if (it < 35) gather(it+1);
        uint32_t boff = (uint32_t)buf*(SGB*4);
        mma_chunk3L(d, aPat + boff, aPat + 2*(SGB*4) + boff,
                       bPat + 4*(SGB*4) + boff, bPat + 6*(SGB*4) + boff);
    }
    __syncthreads();

    // epilogue: bias + g_pre + fused stats
    float* Vs  = (float*)su;        // [128][132]
    float* Ps  = Vs + 16896;
    float* Ps2 = Ps + 512;
#pragma unroll
    for (int mt=0;mt<2;mt++){
        int r0 = warpM*32 + mt*16 + lg;
#pragma unroll
        for (int nt=0;nt<4;nt++){
            int co0 = warpN*32 + nt*8 + lc*2;
            float b0v = cbv[co0], b1v = cbv[co0+1];
            *(float2*)(Vs + r0*132 + co0)     = make_float2(d[mt][nt][0]+b0v, d[mt][nt][1]+b1v);
            *(float2*)(Vs + (r0+8)*132 + co0) = make_float2(d[mt][nt][2]+b0v, d[mt][nt][3]+b1v);
        }
    }
    __syncthreads();
    float* preo = g_pre + (size_t)img*HW*C;
#pragma unroll
    for (int t=0;t<32;t++){
        int idx = tid + t*512;
        int p2 = idx>>7, co = idx&127;
        preo[(pb+p2)*C + co] = Vs[p2*132 + co];
    }
    {
        int co = tid&127, qq = tid>>7;
        float S=0.f, Q=0.f;
#pragma unroll 8
        for (int i=0;i<32;i++){ float v = Vs[(qq*32+i)*132+co]; S += v; Q += v*v; }
        Ps[qq*128+co] = S; Ps2[qq*128+co] = Q;
        __syncthreads();
        if (tid < 128){
            float SS = Ps[tid]+Ps[128+tid]+Ps[256+tid]+Ps[384+tid];
            float QQ = Ps2[tid]+Ps2[128+tid]+Ps2[256+tid]+Ps2[384+tid];
            atomicAdd(&g_sumA[(s*NIMG+img)*128+tid], SS);
            atomicAdd(&g_sqA[(s*NIMG+img)*128+tid], QQ);
        }
    }
}

// ---------------- instance-norm apply ----------------
__global__ void normrelu2_kernel(const float* __restrict__ bg, const float* __restrict__ bb,
                                 float* __restrict__ outbase, int s){
    int img = blockIdx.y;
    int idx = blockIdx.x*blockDim.x + threadIdx.x;
    int c = idx & 127;
    float mu = g_sumA[(s*NIMG+img)*128+c] * (1.f/HW);
    float var = g_sqA[(s*NIMG+img)*128+c] * (1.f/HW) - mu*mu;
    float v = (g_pre[(size_t)img*HW*C + idx]-mu)*rsqrtf(var+EPS)*bg[c] + bb[c];
    outbase[(size_t)img*HW*C + idx] = fmaxf(v, 0.f);
}

// ---------------- projections via HMMA (K=256: xc || xp; NCC skip; ldmatrix) ----------------
#define PJ_SMEM (8*SGB*4)
__global__ __launch_bounds__(512,1) void projH_kernel(const float* __restrict__ xcbase, Ptr5 xps,
                                                      float* __restrict__ out){
    const int img = blockIdx.z;
    const int nco = c_ncos[img];
    const int ct = blockIdx.y;
    if (ct*128 >= nco) return;
    extern __shared__ uint32_t su[];
    uint32_t* AHb[2]={su,         su + SGB};
    uint32_t* ALb[2]={su + 2*SGB, su + 3*SGB};
    uint32_t* BHb[2]={su + 4*SGB, su + 5*SGB};
    uint32_t* BLb[2]={su + 6*SGB, su + 7*SGB};
    const int tid = threadIdx.x;
    const int h0 = blockIdx.x, pb = h0*128;
    const float* xc = xcbase + (size_t)img*HW*C;
    const float* xp = xps.p[img];
    const int px = tid>>2, q4 = tid&3;
    const int wid = tid>>5, lane = tid&31, lg = lane>>2, lc = lane&3;
    const int warpM = wid&3, warpN = wid>>2;
    const int rowbase = c_pjbase[img] + ct*128;
    const int NCC = c_ccend[img];
    const int lr = lane&7, gg = lane>>3;

    const uint32_t sb = smem_u32(su);
    const uint32_t aPat = sb + (uint32_t)(((warpM*32 + (gg&1)*8 + lr)*20 + (gg>>1)*4)*4);
    const uint32_t bPat = sb + (uint32_t)(((warpN*32 + lr)*20 + (gg&1)*4)*4);

    float d[2][4][4];
#pragma unroll
    for (int mt=0;mt<2;mt++)
#pragma unroll
        for (int nt=0;nt<4;nt++)
#pragma unroll
            for (int i=0;i<4;i++) d[mt][nt][i]=0.f;

    float4 gr[2];
    uint4 wbh, wbl;
    auto load_chunk = [&](int cc){
        const float* src = (cc<4) ? (xc + (size_t)(pb+px)*C + cc*32 + q4*8)
                                  : (xp + (size_t)(pb+px)*C + (cc-4)*32 + q4*8);
        gr[0] = ((const float4*)src)[0];
        gr[1] = ((const float4*)src)[1];
        uint32_t base = (uint32_t)((rowbase+px)*128 + cc*16 + q4*4);
        wbh = *(const uint4*)(&g_pjH[base]);
        wbl = *(const uint4*)(&g_pjL[base]);
    };
    auto store_stage = [&](int buf){
        uint32_t hh[4], ll[4];
        bsplit2(make_float2(gr[0].x,gr[0].y), hh[0], ll[0]);
        bsplit2(make_float2(gr[0].z,gr[0].w), hh[1], ll[1]);
        bsplit2(make_float2(gr[1].x,gr[1].y), hh[2], ll[2]);
        bsplit2(make_float2(gr[1].z,gr[1].w), hh[3], ll[3]);
        uint32_t abase = (uint32_t)px*20 + q4*4;
        *(uint4*)(AHb[buf]+abase) = make_uint4(hh[0],hh[1],hh[2],hh[3]);
        *(uint4*)(ALb[buf]+abase) = make_uint4(ll[0],ll[1],ll[2],ll[3]);
        *(uint4*)(BHb[buf]+abase) = wbh;
        *(uint4*)(BLb[buf]+abase) = wbl;
    };

    load_chunk(0); store_stage(0);
    __syncthreads();
    for (int cc=0; cc<NCC; cc++){
        if (cc < NCC-1) load_chunk(cc+1);
        uint32_t boff = (uint32_t)(cc&1)*(SGB*4);
        mma_chunk3L(d, aPat + boff, aPat + 2*(SGB*4) + boff,
                       bPat + 4*(SGB*4) + boff, bPat + 6*(SGB*4) + boff);
        if (cc < NCC-1) store_stage((cc+1)&1);
        __syncthreads();
    }

    float* Vs = (float*)su;   // [128][132]
#pragma unroll
    for (int mt=0;mt<2;mt++){
        int r0 = warpM*32 + mt*16 + lg;
#pragma unroll
        for (int nt=0;nt<4;nt++){
            int co0 = warpN*32 + nt*8 + lc*2;
            *(float2*)(Vs + r0*132 + co0)     = make_float2(d[mt][nt][0], d[mt][nt][1]);
            *(float2*)(Vs + (r0+8)*132 + co0) = make_float2(d[mt][nt][2], d[mt][nt][3]);
        }
    }
    __syncthreads();
    {
        int co = tid>>2, sub = tid&3;
        int cog = ct*128 + co;
        if (cog < nco){
            float* dst = out + (size_t)(c_coff[img]+cog)*HW + pb + sub*32;
#pragma unroll
            for (int j=0;j<8;j++){
                int r = sub*32 + j*4;
                float4 o = make_float4(Vs[r*132+co], Vs[(r+1)*132+co],
                                       Vs[(r+2)*132+co], Vs[(r+3)*132+co]);
                *(float4*)(dst + j*4) = o;
            }
        }
    }
}

// ---------------- final layernorm over W ----------------
__global__ __launch_bounds__(128) void ln_kernel(float* __restrict__ o, const float* __restrict__ lnw,
                                                 const float* __restrict__ lnb){
    __shared__ float ss[4], ssq[4];
    int row = blockIdx.x;
    float* r = o + (size_t)row*128;
    int t = threadIdx.x;
    float v = r[t];
    float s = v, sq = v*v;
#pragma unroll
    for (int off=16; off; off>>=1){
        s  += __shfl_down_sync(0xffffffffu, s, off);
        sq += __shfl_down_sync(0xffffffffu, sq, off);
    }
    int wid = t >> 5, lane = t & 31;
    if (lane==0){ ss[wid]=s; ssq[wid]=sq; }
    __syncthreads();
    float S  = ss[0]+ss[1]+ss[2]+ss[3];
    float SQ = ssq[0]+ssq[1]+ssq[2]+ssq[3];
    float mu = S*(1.f/128.f);
    float var = SQ*(1.f/128.f) - mu*mu;
    r[t] = (v-mu)*rsqrtf(var+EPS)*lnw[t] + lnb[t];
}

// ---------------- host orchestration ----------------
extern "C" void kernel_launch(void* const* d_in, const int* in_sizes, int n_in,
                              void* d_out, int out_size){
    (void)in_sizes; (void)n_in; (void)out_size;
    const float* x[5];
    for (int i=0;i<5;i++) x[i] = (const float*)d_in[i];
    const float* cw[2] = {(const float*)d_in[5],  (const float*)d_in[11]};
    const float* cb[2] = {(const float*)d_in[6],  (const float*)d_in[12]};
    const float* ow[2] = {(const float*)d_in[7],  (const float*)d_in[13]};
    const float* mw[2] = {(const float*)d_in[8],  (const float*)d_in[14]};
    const float* bg[2] = {(const float*)d_in[9],  (const float*)d_in[15]};
    const float* bb[2] = {(const float*)d_in[10], (const float*)d_in[16]};
    const float* pwa[5] = {(const float*)d_in[17], (const float*)d_in[18], (const float*)d_in[19],
                           (const float*)d_in[21], (const float*)d_in[23]};
    const float* pwb[5] = {nullptr, nullptr, (const float*)d_in[20],
                           (const float*)d_in[22], (const float*)d_in[24]};
    const float* lnw = (const float*)d_in[25];
    const float* lnb = (const float*)d_in[26];
    float* outp = (float*)d_out;

    float *pA=nullptr, *pB=nullptr;
    cudaGetSymbolAddress((void**)&pA, g_bufA);
    cudaGetSymbolAddress((void**)&pB, g_bufB);

    Ptr5 xs0, xsA, wav, wbv;
    for (int i=0;i<5;i++){
        xs0.p[i] = x[i];
        xsA.p[i] = pA + (size_t)i*HW*C;
        wav.p[i] = pwa[i];
        wbv.p[i] = pwb[i];
    }

    cudaFuncSetAttribute(offcv3_kernel, cudaFuncAttributeMaxDynamicSharedMemorySize, OC_SMEM);
    cudaFuncSetAttribute(sg7_kernel, cudaFuncAttributeMaxDynamicSharedMemorySize, SG7_SMEM);
    cudaFuncSetAttribute(projH_kernel, cudaFuncAttributeMaxDynamicSharedMemorySize, PJ_SMEM);
    // offcv only: max carveout so two 102KB CTAs can co-reside (regs allow it).
    cudaFuncSetAttribute(offcv3_kernel, cudaFuncAttributePreferredSharedMemoryCarveout, 100);

    prep_wtP_kernel<<<(KK*4*128*16+255)/256, 256>>>(cw[0], cw[1]);
    prep_effP_kernel<<<(KK*4*32*16+255)/256, 256>>>(cw[0], ow[0], mw[0], cb[0], 0);
    prep_effP_kernel<<<(KK*4*32*16+255)/256, 256>>>(cw[1], ow[1], mw[1], cb[1], 1);
    prep_pj_kernel<<<(1280*128+255)/256, 256>>>(wav, wbv);
    zero_sums_kernel<<<5, 256>>>();

    // stage 1 (all images)
    offcv3_kernel<<<dim3(128,5), 256, OC_SMEM>>>(xs0, 0);
    sg7_kernel<<<dim3(128,5), 512, SG7_SMEM>>>(xs0, cb[0], 0, 0);
    normrelu2_kernel<<<dim3(HW*C/256,5), 256>>>(bg[0], bb[0], pA, 0);
    // stage 2 (all images)
    offcv3_kernel<<<dim3(128,5), 256, OC_SMEM>>>(xsA, 1);
    sg7_kernel<<<dim3(128,5), 512, SG7_SMEM>>>(xsA, cb[1], 1, 1);
    normrelu2_kernel<<<dim3(HW*C/256,5), 256>>>(bg[1], bb[1], pB, 1);
    // projections + final LN
    projH_kernel<<<dim3(128,3,5), 512, PJ_SMEM>>>(pB, xs0, outp);
    ln_kernel<<<768*Hh, 128>>>(outp, lnw, lnb);
}